// round 2
// baseline (speedup 1.0000x reference)
#include <cuda_runtime.h>
#include <cstdint>

#define B_MAX   8
#define P_MAX   140000
#define NBINS   4096
#define CAP     16384      // compact buffer per batch (power of two, bitonic sort size)
#define NMS_K   5000       // candidates considered by NMS
#define TOPK    750        // rows emitted per class
#define CONF_TH 0.05f
#define NMS_TH  0.3f

// ---------------- scratch (static device globals; no allocation) ----------------
__device__ float              g_scores[B_MAX * P_MAX];
__device__ unsigned int       g_hist  [B_MAX * NBINS];
__device__ int                g_cnt   [B_MAX];
__device__ int                g_cutbin[B_MAX];
__device__ unsigned long long g_keys  [B_MAX * CAP];
__device__ float              g_cscore[B_MAX * NMS_K];
__device__ float4             g_cbox  [B_MAX * NMS_K];
__device__ float              g_carea [B_MAX * NMS_K];

// ---------------- init: zero output + scratch ----------------
__global__ void init_kernel(float* __restrict__ out, int out_size, int B) {
    int stride = gridDim.x * blockDim.x;
    int t = blockIdx.x * blockDim.x + threadIdx.x;
    for (int i = t; i < out_size; i += stride) out[i] = 0.0f;
    for (int i = t; i < B * NBINS; i += stride) g_hist[i] = 0u;
    for (int i = t; i < B; i += stride) g_cnt[i] = 0;
    for (int i = t; i < B * CAP; i += stride) g_keys[i] = ~0ull;
}

// ---------------- scores: softmax class-1 prob, threshold, histogram ----------------
__global__ void score_kernel(const float* __restrict__ conf, int B, int P) {
    int i = blockIdx.x * blockDim.x + threadIdx.x;
    int n = B * P;
    if (i >= n) return;
    float2 c = reinterpret_cast<const float2*>(conf)[i];
    float m  = fmaxf(c.x, c.y);
    float e0 = expf(c.x - m);
    float e1 = expf(c.y - m);
    float s  = __fdiv_rn(e1, e0 + e1);          // == jax.nn.softmax(...)[...,1]
    float th = (s > CONF_TH) ? s : -1.0f;
    g_scores[i] = th;
    if (th > 0.0f) {
        int bin = (int)(th * (float)NBINS);
        bin = (bin > NBINS - 1) ? NBINS - 1 : (bin < 0 ? 0 : bin);
        atomicAdd(&g_hist[(i / P) * NBINS + bin], 1u);
    }
}

// ---------------- cutoff: smallest bin t s.t. suffix count >= NMS_K ----------------
__global__ void cutoff_kernel(int B) {
    int b = blockIdx.x;
    __shared__ unsigned int csum[256];
    int tid = threadIdx.x;
    unsigned int sum = 0;
    #pragma unroll
    for (int i = 0; i < NBINS / 256; i++) sum += g_hist[b * NBINS + tid * (NBINS / 256) + i];
    csum[tid] = sum;
    __syncthreads();
    if (tid == 0) {
        unsigned int acc = 0;
        int c = 255;
        for (; c >= 0; c--) {
            if (acc + csum[c] >= (unsigned)NMS_K) break;
            acc += csum[c];
        }
        int cut = 0;
        if (c >= 0) {
            int bin = c * (NBINS / 256) + (NBINS / 256) - 1;
            for (; bin >= c * (NBINS / 256); bin--) {
                acc += g_hist[b * NBINS + bin];
                if (acc >= (unsigned)NMS_K) break;
            }
            cut = (bin < c * (NBINS / 256)) ? c * (NBINS / 256) : bin;
        }
        g_cutbin[b] = cut;
    }
}

// ---------------- compact: gather candidates above cutoff as sortable keys ----------------
__global__ void compact_kernel(int B, int P) {
    int i = blockIdx.x * blockDim.x + threadIdx.x;
    int n = B * P;
    if (i >= n) return;
    float th = g_scores[i];
    if (th <= 0.0f) return;
    int b = i / P;
    int bin = (int)(th * (float)NBINS);
    bin = (bin > NBINS - 1) ? NBINS - 1 : (bin < 0 ? 0 : bin);
    if (bin >= g_cutbin[b]) {
        int pos = atomicAdd(&g_cnt[b], 1);
        if (pos < CAP) {
            unsigned int kb = __float_as_uint(th);       // positive floats: bits order == value order
            unsigned long long key = ((unsigned long long)(~kb) << 32) | (unsigned int)(i - b * P);
            g_keys[b * CAP + pos] = key;                 // ascending sort => desc score, asc index
        }
    }
}

// ---------------- per-batch bitonic sort of CAP keys + decode top NMS_K boxes ----------------
__global__ void sort_kernel(const float* __restrict__ loc, const float* __restrict__ prior,
                            int B, int P) {
    extern __shared__ unsigned long long sm[];
    int b = blockIdx.x, tid = threadIdx.x, T = blockDim.x;
    for (int i = tid; i < CAP; i += T) sm[i] = g_keys[b * CAP + i];
    __syncthreads();
    for (int k = 2; k <= CAP; k <<= 1) {
        for (int j = k >> 1; j > 0; j >>= 1) {
            for (int i = tid; i < CAP; i += T) {
                int ixj = i ^ j;
                if (ixj > i) {
                    unsigned long long a = sm[i], c = sm[ixj];
                    bool up = ((i & k) == 0);
                    if ((a > c) == up) { sm[i] = c; sm[ixj] = a; }
                }
            }
            __syncthreads();
        }
    }
    // decode the top NMS_K candidates
    for (int i = tid; i < NMS_K; i += T) {
        unsigned long long key = sm[i];
        unsigned int idx = (unsigned int)key;
        int o = b * NMS_K + i;
        if (idx < (unsigned int)P) {
            float  sc = g_scores[b * P + idx];
            float4 l  = reinterpret_cast<const float4*>(loc)[(size_t)b * P + idx];
            float4 pr = reinterpret_cast<const float4*>(prior)[idx];
            float cx = pr.x + l.x * 0.1f * pr.z;
            float cy = pr.y + l.y * 0.1f * pr.w;
            float w  = pr.z * expf(l.z * 0.2f);
            float h  = pr.w * expf(l.w * 0.2f);
            float x1 = cx - w * 0.5f;
            float y1 = cy - h * 0.5f;
            float x2 = x1 + w;
            float y2 = y1 + h;
            g_cscore[o] = sc;
            g_cbox[o]   = make_float4(x1, y1, x2, y2);
            g_carea[o]  = (x2 - x1) * (y2 - y1);
        } else {
            g_cscore[o] = -1.0f;
            g_cbox[o]   = make_float4(0.f, 0.f, 0.f, 0.f);
            g_carea[o]  = 0.0f;
        }
    }
}

// ---------------- greedy NMS: sorted order => argmax == first unsuppressed ----------------
__global__ void nms_kernel(float* __restrict__ out, int B) {
    extern __shared__ unsigned char smraw[];
    float4* box  = (float4*)smraw;
    float*  s    = (float*)(smraw + (size_t)NMS_K * sizeof(float4));
    float*  area = s + NMS_K;
    __shared__ int    sh_head, sh_done;
    __shared__ float4 sh_box;
    __shared__ float  sh_area;

    int b = blockIdx.x, tid = threadIdx.x, T = blockDim.x;
    for (int i = tid; i < NMS_K; i += T) {
        box[i]  = g_cbox[b * NMS_K + i];
        s[i]    = g_cscore[b * NMS_K + i];
        area[i] = g_carea[b * NMS_K + i];
    }
    if (tid == 0) sh_head = 0;
    __syncthreads();

    float* orow = out + ((size_t)b * 2 + 1) * TOPK * 5;   // class 1 rows
    for (int k = 0; k < TOPK; k++) {
        if (tid == 0) {
            int h = sh_head;
            while (h < NMS_K && s[h] <= 0.0f) h++;
            if (h >= NMS_K) {
                sh_done = 1;
            } else {
                sh_done = 0;
                float4 bb = box[h];
                float  sc = s[h];
                orow[k * 5 + 0] = sc;
                orow[k * 5 + 1] = bb.x;
                orow[k * 5 + 2] = bb.y;
                orow[k * 5 + 3] = bb.z;
                orow[k * 5 + 4] = bb.w;
                sh_box  = bb;
                sh_area = area[h];
                s[h]    = -1.0f;
                sh_head = h + 1;
            }
        }
        __syncthreads();
        if (sh_done) break;
        float4 hb = sh_box;
        float  ha = sh_area;
        int    h0 = sh_head;
        for (int j = h0 + tid; j < NMS_K; j += T) {
            if (s[j] <= 0.0f) continue;
            float4 bj  = box[j];
            float xx1 = fmaxf(bj.x, hb.x), yy1 = fmaxf(bj.y, hb.y);
            float xx2 = fminf(bj.z, hb.z), yy2 = fminf(bj.w, hb.w);
            float inter = fmaxf(xx2 - xx1, 0.0f) * fmaxf(yy2 - yy1, 0.0f);
            float uni   = area[j] - inter + ha;
            float iou   = __fdiv_rn(inter, uni);
            if (iou > NMS_TH) s[j] = -1.0f;
        }
        __syncthreads();
    }
}

// ---------------- launch ----------------
extern "C" void kernel_launch(void* const* d_in, const int* in_sizes, int n_in,
                              void* d_out, int out_size) {
    const float* loc   = (const float*)d_in[0];   // [B,P,4]
    const float* conf  = (const float*)d_in[1];   // [B,P,2]
    const float* prior = (const float*)d_in[2];   // [P,4]

    int P = in_sizes[2] / 4;
    int B = in_sizes[1] / (2 * P);
    if (B > B_MAX) B = B_MAX;
    if (P > P_MAX) P = P_MAX;

    float* out = (float*)d_out;

    // opt-in dynamic smem (>48KB) for sort + NMS
    static const size_t SORT_SMEM = (size_t)CAP * sizeof(unsigned long long);     // 128 KB
    static const size_t NMS_SMEM  = (size_t)NMS_K * (sizeof(float4) + 2 * sizeof(float)); // 120 KB
    cudaFuncSetAttribute(sort_kernel, cudaFuncAttributeMaxDynamicSharedMemorySize, (int)SORT_SMEM);
    cudaFuncSetAttribute(nms_kernel,  cudaFuncAttributeMaxDynamicSharedMemorySize, (int)NMS_SMEM);

    int n = B * P;
    init_kernel<<<512, 256>>>(out, out_size, B);
    score_kernel<<<(n + 255) / 256, 256>>>(conf, B, P);
    cutoff_kernel<<<B, 256>>>(B);
    compact_kernel<<<(n + 255) / 256, 256>>>(B, P);
    sort_kernel<<<B, 1024, SORT_SMEM>>>(loc, prior, B, P);
    nms_kernel<<<B, 1024, NMS_SMEM>>>(out, B);
}

// round 3
// speedup vs baseline: 2.0148x; 2.0148x over previous
#include <cuda_runtime.h>
#include <cstdint>

#define B_MAX   8
#define P_MAX   140000
#define NBINS   4096
#define CAP     8192       // compact buffer per batch (power of two, bitonic size)
#define NMS_K   5000       // candidates considered by NMS
#define NWORDS  157        // ceil(5000/32)
#define ROWW    160        // padded words per suppression-matrix row
#define TOPK    750        // rows emitted per class
#define CONF_TH 0.05f
#define NMS_TH  0.3f

// ---------------- scratch (static device globals; no allocation) ----------------
__device__ float              g_scores[B_MAX * P_MAX];
__device__ unsigned int       g_hist  [B_MAX * NBINS];
__device__ int                g_cnt   [B_MAX];
__device__ int                g_cutbin[B_MAX];
__device__ unsigned long long g_keys  [B_MAX * CAP];
__device__ float              g_cscore[B_MAX * NMS_K];
__device__ float4             g_cbox  [B_MAX * NMS_K];
__device__ float              g_carea [B_MAX * NMS_K];
__device__ unsigned int       g_mat   [(size_t)B_MAX * NMS_K * ROWW];   // ~25.6 MB

// ---------------- init: zero output + scratch ----------------
__global__ void init_kernel(float* __restrict__ out, int out_size, int B) {
    int stride = gridDim.x * blockDim.x;
    int t = blockIdx.x * blockDim.x + threadIdx.x;
    for (int i = t; i < out_size; i += stride) out[i] = 0.0f;
    for (int i = t; i < B * NBINS; i += stride) g_hist[i] = 0u;
    for (int i = t; i < B; i += stride) g_cnt[i] = 0;
    for (int i = t; i < B * CAP; i += stride) g_keys[i] = ~0ull;
}

// ---------------- scores: softmax class-1 prob, threshold, histogram ----------------
__global__ void score_kernel(const float* __restrict__ conf, int P) {
    int b = blockIdx.y;
    int idx = (blockIdx.x * blockDim.x + threadIdx.x) * 2;
    if (idx >= P) return;
    size_t off = (size_t)b * P + idx;                    // even
    float4 c = reinterpret_cast<const float4*>(conf)[off >> 1];
    #pragma unroll
    for (int q = 0; q < 2; q++) {
        if (idx + q >= P) break;
        float c0 = q ? c.z : c.x;
        float c1 = q ? c.w : c.y;
        float m  = fmaxf(c0, c1);
        float e0 = expf(c0 - m);
        float e1 = expf(c1 - m);
        float s  = __fdiv_rn(e1, e0 + e1);               // == softmax(...)[...,1]
        float th = (s > CONF_TH) ? s : -1.0f;
        g_scores[off + q] = th;
        if (th > 0.0f) {
            int bin = (int)(th * (float)NBINS);
            bin = (bin > NBINS - 1) ? NBINS - 1 : (bin < 0 ? 0 : bin);
            atomicAdd(&g_hist[b * NBINS + bin], 1u);
        }
    }
}

// ---------------- cutoff: smallest bin t s.t. suffix count >= NMS_K ----------------
__global__ void cutoff_kernel() {
    int b = blockIdx.x;
    __shared__ unsigned int csum[256];
    int tid = threadIdx.x;
    unsigned int sum = 0;
    #pragma unroll
    for (int i = 0; i < NBINS / 256; i++) sum += g_hist[b * NBINS + tid * (NBINS / 256) + i];
    csum[tid] = sum;
    __syncthreads();
    if (tid == 0) {
        unsigned int acc = 0;
        int c = 255;
        for (; c >= 0; c--) {
            if (acc + csum[c] >= (unsigned)NMS_K) break;
            acc += csum[c];
        }
        int cut = 0;
        if (c >= 0) {
            int bin = c * (NBINS / 256) + (NBINS / 256) - 1;
            for (; bin >= c * (NBINS / 256); bin--) {
                acc += g_hist[b * NBINS + bin];
                if (acc >= (unsigned)NMS_K) break;
            }
            cut = (bin < c * (NBINS / 256)) ? c * (NBINS / 256) : bin;
        }
        g_cutbin[b] = cut;
    }
}

// ---------------- compact: warp-aggregated gather of candidates above cutoff ----------------
__global__ void compact_kernel(int P) {
    int b = blockIdx.y;
    int lane = threadIdx.x & 31;
    int base = (blockIdx.x * blockDim.x + threadIdx.x) * 4;
    int cut  = g_cutbin[b];
    unsigned long long keys[4];
    int c = 0;
    if (base < P) {
        float4 s4 = *reinterpret_cast<const float4*>(&g_scores[(size_t)b * P + base]);
        float sv[4] = {s4.x, s4.y, s4.z, s4.w};
        #pragma unroll
        for (int q = 0; q < 4; q++) {
            if (base + q < P) {
                float th = sv[q];
                if (th > 0.0f) {
                    int bin = (int)(th * (float)NBINS);
                    bin = (bin > NBINS - 1) ? NBINS - 1 : (bin < 0 ? 0 : bin);
                    if (bin >= cut) {
                        unsigned kb = __float_as_uint(th);
                        keys[c++] = ((unsigned long long)(~kb) << 32) | (unsigned)(base + q);
                    }
                }
            }
        }
    }
    unsigned cnt = (unsigned)c;
    #pragma unroll
    for (int d = 1; d < 32; d <<= 1) {
        unsigned n = __shfl_up_sync(0xffffffffu, cnt, d);
        if (lane >= d) cnt += n;
    }
    unsigned tot = __shfl_sync(0xffffffffu, cnt, 31);
    int basepos = 0;
    if (lane == 31 && tot) basepos = atomicAdd(&g_cnt[b], (int)tot);
    basepos = __shfl_sync(0xffffffffu, basepos, 31);
    int pos = basepos + (int)(cnt - (unsigned)c);
    for (int q = 0; q < c; q++, pos++)
        if (pos < CAP) g_keys[(size_t)b * CAP + pos] = keys[q];
}

// ---------------- per-batch bitonic sort of CAP keys + decode top NMS_K boxes ----------------
__global__ void sort_kernel(const float* __restrict__ loc, const float* __restrict__ prior,
                            int P) {
    extern __shared__ unsigned long long sm[];
    int b = blockIdx.x, tid = threadIdx.x, T = blockDim.x;
    for (int i = tid; i < CAP; i += T) sm[i] = g_keys[(size_t)b * CAP + i];
    __syncthreads();
    for (int k = 2; k <= CAP; k <<= 1) {
        for (int j = k >> 1; j > 0; j >>= 1) {
            for (int i = tid; i < CAP; i += T) {
                int ixj = i ^ j;
                if (ixj > i) {
                    unsigned long long a = sm[i], c = sm[ixj];
                    bool up = ((i & k) == 0);
                    if ((a > c) == up) { sm[i] = c; sm[ixj] = a; }
                }
            }
            __syncthreads();
        }
    }
    for (int i = tid; i < NMS_K; i += T) {
        unsigned long long key = sm[i];
        unsigned int idx = (unsigned int)key;
        int o = b * NMS_K + i;
        if (idx < (unsigned int)P) {
            float  sc = g_scores[(size_t)b * P + idx];
            float4 l  = reinterpret_cast<const float4*>(loc)[(size_t)b * P + idx];
            float4 pr = reinterpret_cast<const float4*>(prior)[idx];
            float cx = pr.x + l.x * 0.1f * pr.z;
            float cy = pr.y + l.y * 0.1f * pr.w;
            float w  = pr.z * expf(l.z * 0.2f);
            float h  = pr.w * expf(l.w * 0.2f);
            float x1 = cx - w * 0.5f;
            float y1 = cy - h * 0.5f;
            float x2 = x1 + w;
            float y2 = y1 + h;
            g_cscore[o] = sc;
            g_cbox[o]   = make_float4(x1, y1, x2, y2);
            g_carea[o]  = (x2 - x1) * (y2 - y1);
        } else {
            g_cscore[o] = -1.0f;
            g_cbox[o]   = make_float4(0.f, 0.f, 0.f, 0.f);
            g_carea[o]  = 0.0f;
        }
    }
}

// ---------------- suppression bitmatrix: bit j of row i set iff iou(i,j)>0.3, j>i ----------------
#define MTILE 1024
#define MROWS 64
__global__ __launch_bounds__(256) void matrix_kernel() {
    __shared__ float4 tb[MTILE];
    __shared__ float  ta[MTILE];
    int b  = blockIdx.y;
    int i0 = blockIdx.x * MROWS;
    int tid = threadIdx.x, lane = tid & 31, wid = tid >> 5;   // 8 warps

    float4 rb[8]; float ra[8];
    #pragma unroll
    for (int r = 0; r < 8; r++) {
        int i = i0 + wid * 8 + r;
        if (i < NMS_K) { rb[r] = g_cbox[b * NMS_K + i]; ra[r] = g_carea[b * NMS_K + i]; }
        else           { rb[r] = make_float4(0,0,0,0);  ra[r] = 0.f; }
    }

    int jt0 = i0 & ~(MTILE - 1);
    for (int jt = jt0; jt < NMS_K; jt += MTILE) {
        __syncthreads();
        for (int q = tid; q < MTILE; q += 256) {
            int j = jt + q;
            if (j < NMS_K) { tb[q] = g_cbox[b * NMS_K + j]; ta[q] = g_carea[b * NMS_K + j]; }
            else           { tb[q] = make_float4(0,0,0,0);  ta[q] = 0.f; }
        }
        __syncthreads();
        int jend = min(jt + MTILE, ROWW * 32);
        #pragma unroll
        for (int r = 0; r < 8; r++) {
            int i = i0 + wid * 8 + r;
            if (i >= NMS_K) break;
            int wlo = i >> 5;
            float4 bi = rb[r]; float ai = ra[r];
            size_t rowb = ((size_t)(b * NMS_K + i)) * ROWW;
            for (int jj = jt; jj < jend; jj += 32) {
                if ((jj >> 5) < wlo) continue;
                int j = jj + lane;
                bool flag = false;
                if (j > i && j < NMS_K) {
                    float4 bj = tb[j - jt]; float aj = ta[j - jt];
                    float xx1 = fmaxf(bj.x, bi.x), yy1 = fmaxf(bj.y, bi.y);
                    float xx2 = fminf(bj.z, bi.z), yy2 = fminf(bj.w, bi.w);
                    float inter = fmaxf(xx2 - xx1, 0.f) * fmaxf(yy2 - yy1, 0.f);
                    float uni   = aj - inter + ai;
                    float d     = fmaf(-NMS_TH, uni, inter);
                    if (fabsf(d) <= 1e-6f * fabsf(uni))
                        flag = __fdiv_rn(inter, uni) > NMS_TH;   // exact ref semantics at boundary
                    else
                        flag = d > 0.f;
                }
                unsigned wm = __ballot_sync(0xffffffffu, flag);
                if (lane == 0) g_mat[rowb + (jj >> 5)] = wm;
            }
        }
    }
}

// ---------------- greedy sweep: 1 warp/batch, register+smem bitmask chain ----------------
__global__ void sweep_kernel(float* __restrict__ out) {
    extern __shared__ unsigned char smraw[];
    float4*   sbox    = (float4*)smraw;
    float*    sscore  = (float*)(smraw + (size_t)NMS_K * sizeof(float4));
    unsigned* removed = (unsigned*)(sscore + NMS_K);
    unsigned* validw  = removed + ROWW;

    int b = blockIdx.x, tid = threadIdx.x, lane = tid & 31, wid = tid >> 5;
    for (int i = tid; i < NMS_K; i += blockDim.x) {
        sbox[i]   = g_cbox[b * NMS_K + i];
        sscore[i] = g_cscore[b * NMS_K + i];
    }
    if (tid < ROWW) removed[tid] = 0u;
    __syncthreads();
    for (int w = wid; w < ROWW; w += (blockDim.x >> 5)) {
        int idx = w * 32 + lane;
        unsigned m = __ballot_sync(0xffffffffu, (idx < NMS_K) && (sscore[idx] > 0.0f));
        if (lane == 0) validw[w] = m;
    }
    __syncthreads();
    if (wid != 0) return;

    int emitted = 0;
    float* orow = out + ((size_t)b * 2 + 1) * TOPK * 5;   // class 1
    for (int w = 0; w < NWORDS && emitted < TOPK; w++) {
        int iw = w * 32 + lane;
        unsigned pre = (iw < NMS_K) ? g_mat[((size_t)(b * NMS_K + iw)) * ROWW + w] : 0u;
        unsigned cur = removed[w];
        unsigned avail = (~cur) & validw[w];
        while (avail && emitted < TOPK) {
            int bit = __ffs(avail) - 1;
            int i = w * 32 + bit;
            if (lane == 0) {
                float4 bb = sbox[i];
                float* r = orow + emitted * 5;
                r[0] = sscore[i];
                r[1] = bb.x; r[2] = bb.y; r[3] = bb.z; r[4] = bb.w;
            }
            emitted++;
            unsigned rw = __shfl_sync(0xffffffffu, pre, bit);   // row i, current word
            size_t rowb = ((size_t)(b * NMS_K + i)) * ROWW;
            for (int k = w + 1 + lane; k < ROWW; k += 32)
                removed[k] |= g_mat[rowb + k];                  // future words
            avail &= ~(1u << bit);
            avail &= ~rw;
        }
        __syncwarp();   // row ORs visible before next word's removed[] read
    }
}

// ---------------- launch ----------------
extern "C" void kernel_launch(void* const* d_in, const int* in_sizes, int n_in,
                              void* d_out, int out_size) {
    const float* loc   = (const float*)d_in[0];   // [B,P,4]
    const float* conf  = (const float*)d_in[1];   // [B,P,2]
    const float* prior = (const float*)d_in[2];   // [P,4]

    int P = in_sizes[2] / 4;
    int B = in_sizes[1] / (2 * P);
    if (B > B_MAX) B = B_MAX;
    if (P > P_MAX) P = P_MAX;

    float* out = (float*)d_out;

    static const size_t SORT_SMEM  = (size_t)CAP * sizeof(unsigned long long);              // 64 KB
    static const size_t SWEEP_SMEM = (size_t)NMS_K * (sizeof(float4) + sizeof(float))
                                   + 2 * ROWW * sizeof(unsigned);                            // ~101 KB
    cudaFuncSetAttribute(sort_kernel,  cudaFuncAttributeMaxDynamicSharedMemorySize, (int)SORT_SMEM);
    cudaFuncSetAttribute(sweep_kernel, cudaFuncAttributeMaxDynamicSharedMemorySize, (int)SWEEP_SMEM);

    init_kernel<<<256, 256>>>(out, out_size, B);

    dim3 gscore((P + 511) / 512, B);
    score_kernel<<<gscore, 256>>>(conf, P);

    cutoff_kernel<<<B, 256>>>();

    dim3 gcomp((P + 1023) / 1024, B);
    compact_kernel<<<gcomp, 256>>>(P);

    sort_kernel<<<B, 1024, SORT_SMEM>>>(loc, prior, P);

    dim3 gmat((NMS_K + MROWS - 1) / MROWS, B);
    matrix_kernel<<<gmat, 256>>>();

    sweep_kernel<<<B, 256, SWEEP_SMEM>>>(out);
}

// round 4
// speedup vs baseline: 3.3750x; 1.6751x over previous
#include <cuda_runtime.h>
#include <cstdint>

#define B_MAX   8
#define P_MAX   140000
#define NBINS   4096
#define CAP     8192       // compact buffer per batch (power of two, bitonic size)
#define NMS_K   5000       // candidates considered by NMS
#define NWORDS  157        // ceil(5000/32)
#define PAD     5120       // padded row length (i-dim) of transposed matrix
#define TOPK    750        // rows emitted per class
#define CONF_TH 0.05f
#define NMS_TH  0.3f
#define FULL    0xffffffffu

// ---------------- scratch (static device globals; no allocation) ----------------
__device__ float              g_scores[B_MAX * P_MAX];
__device__ unsigned int       g_hist  [B_MAX * NBINS];
__device__ int                g_cnt   [B_MAX];
__device__ int                g_cutbin[B_MAX];
__device__ unsigned long long g_keys  [B_MAX * CAP];
__device__ float              g_cscore[B_MAX * NMS_K];
__device__ float4             g_cbox  [B_MAX * NMS_K];
__device__ float              g_carea [B_MAX * NMS_K];
// transposed suppression matrix: g_matT[(b*NWORDS + w)*PAD + i] = 32 bits (j = w*32+lane)
__device__ unsigned int       g_matT  [(size_t)B_MAX * NWORDS * PAD];

// ---------------- init: zero output + scratch ----------------
__global__ void init_kernel(float* __restrict__ out, int out_size, int B) {
    int stride = gridDim.x * blockDim.x;
    int t = blockIdx.x * blockDim.x + threadIdx.x;
    for (int i = t; i < out_size; i += stride) out[i] = 0.0f;
    for (int i = t; i < B * NBINS; i += stride) g_hist[i] = 0u;
    for (int i = t; i < B; i += stride) g_cnt[i] = 0;
    for (int i = t; i < B * CAP; i += stride) g_keys[i] = ~0ull;
}

// ---------------- scores: softmax class-1 prob, threshold, histogram ----------------
__global__ void score_kernel(const float* __restrict__ conf, int P) {
    int b = blockIdx.y;
    int idx = (blockIdx.x * blockDim.x + threadIdx.x) * 2;
    if (idx >= P) return;
    size_t off = (size_t)b * P + idx;                    // even
    float4 c = reinterpret_cast<const float4*>(conf)[off >> 1];
    #pragma unroll
    for (int q = 0; q < 2; q++) {
        if (idx + q >= P) break;
        float c0 = q ? c.z : c.x;
        float c1 = q ? c.w : c.y;
        float m  = fmaxf(c0, c1);
        float e0 = expf(c0 - m);
        float e1 = expf(c1 - m);
        float s  = __fdiv_rn(e1, e0 + e1);               // == softmax(...)[...,1]
        float th = (s > CONF_TH) ? s : -1.0f;
        g_scores[off + q] = th;
        if (th > 0.0f) {
            int bin = (int)(th * (float)NBINS);
            bin = (bin > NBINS - 1) ? NBINS - 1 : (bin < 0 ? 0 : bin);
            atomicAdd(&g_hist[b * NBINS + bin], 1u);
        }
    }
}

// ---------------- cutoff: smallest bin t s.t. suffix count >= NMS_K ----------------
__global__ void cutoff_kernel() {
    int b = blockIdx.x;
    __shared__ unsigned int csum[256];
    int tid = threadIdx.x;
    unsigned int sum = 0;
    #pragma unroll
    for (int i = 0; i < NBINS / 256; i++) sum += g_hist[b * NBINS + tid * (NBINS / 256) + i];
    csum[tid] = sum;
    __syncthreads();
    if (tid == 0) {
        unsigned int acc = 0;
        int c = 255;
        for (; c >= 0; c--) {
            if (acc + csum[c] >= (unsigned)NMS_K) break;
            acc += csum[c];
        }
        int cut = 0;
        if (c >= 0) {
            int bin = c * (NBINS / 256) + (NBINS / 256) - 1;
            for (; bin >= c * (NBINS / 256); bin--) {
                acc += g_hist[b * NBINS + bin];
                if (acc >= (unsigned)NMS_K) break;
            }
            cut = (bin < c * (NBINS / 256)) ? c * (NBINS / 256) : bin;
        }
        g_cutbin[b] = cut;
    }
}

// ---------------- compact: warp-aggregated gather of candidates above cutoff ----------------
__global__ void compact_kernel(int P) {
    int b = blockIdx.y;
    int lane = threadIdx.x & 31;
    int base = (blockIdx.x * blockDim.x + threadIdx.x) * 4;
    int cut  = g_cutbin[b];
    unsigned long long keys[4];
    int c = 0;
    if (base < P) {
        float4 s4 = *reinterpret_cast<const float4*>(&g_scores[(size_t)b * P + base]);
        float sv[4] = {s4.x, s4.y, s4.z, s4.w};
        #pragma unroll
        for (int q = 0; q < 4; q++) {
            if (base + q < P) {
                float th = sv[q];
                if (th > 0.0f) {
                    int bin = (int)(th * (float)NBINS);
                    bin = (bin > NBINS - 1) ? NBINS - 1 : (bin < 0 ? 0 : bin);
                    if (bin >= cut) {
                        unsigned kb = __float_as_uint(th);
                        keys[c++] = ((unsigned long long)(~kb) << 32) | (unsigned)(base + q);
                    }
                }
            }
        }
    }
    unsigned cnt = (unsigned)c;
    #pragma unroll
    for (int d = 1; d < 32; d <<= 1) {
        unsigned n = __shfl_up_sync(FULL, cnt, d);
        if (lane >= d) cnt += n;
    }
    unsigned tot = __shfl_sync(FULL, cnt, 31);
    int basepos = 0;
    if (lane == 31 && tot) basepos = atomicAdd(&g_cnt[b], (int)tot);
    basepos = __shfl_sync(FULL, basepos, 31);
    int pos = basepos + (int)(cnt - (unsigned)c);
    for (int q = 0; q < c; q++, pos++)
        if (pos < CAP) g_keys[(size_t)b * CAP + pos] = keys[q];
}

// ---------------- per-batch bitonic sort of CAP keys + decode top NMS_K boxes ----------------
__global__ void sort_kernel(const float* __restrict__ loc, const float* __restrict__ prior,
                            int P) {
    extern __shared__ unsigned long long sm[];
    int b = blockIdx.x, tid = threadIdx.x, T = blockDim.x;
    for (int i = tid; i < CAP; i += T) sm[i] = g_keys[(size_t)b * CAP + i];
    __syncthreads();
    for (int k = 2; k <= CAP; k <<= 1) {
        for (int j = k >> 1; j > 0; j >>= 1) {
            for (int i = tid; i < CAP; i += T) {
                int ixj = i ^ j;
                if (ixj > i) {
                    unsigned long long a = sm[i], c = sm[ixj];
                    bool up = ((i & k) == 0);
                    if ((a > c) == up) { sm[i] = c; sm[ixj] = a; }
                }
            }
            __syncthreads();
        }
    }
    for (int i = tid; i < NMS_K; i += T) {
        unsigned long long key = sm[i];
        unsigned int idx = (unsigned int)key;
        int o = b * NMS_K + i;
        if (idx < (unsigned int)P) {
            float  sc = g_scores[(size_t)b * P + idx];
            float4 l  = reinterpret_cast<const float4*>(loc)[(size_t)b * P + idx];
            float4 pr = reinterpret_cast<const float4*>(prior)[idx];
            float cx = pr.x + l.x * 0.1f * pr.z;
            float cy = pr.y + l.y * 0.1f * pr.w;
            float w  = pr.z * expf(l.z * 0.2f);
            float h  = pr.w * expf(l.w * 0.2f);
            float x1 = cx - w * 0.5f;
            float y1 = cy - h * 0.5f;
            float x2 = x1 + w;
            float y2 = y1 + h;
            g_cscore[o] = sc;
            g_cbox[o]   = make_float4(x1, y1, x2, y2);
            g_carea[o]  = (x2 - x1) * (y2 - y1);
        } else {
            g_cscore[o] = -1.0f;
            g_cbox[o]   = make_float4(0.f, 0.f, 0.f, 0.f);
            g_carea[o]  = 0.0f;
        }
    }
}

// ---------------- suppression bitmatrix (transposed): g_matT[w][i] bit j' = iou(i, w*32+j')>0.3, j>i ----------------
#define ITILE 128
__global__ __launch_bounds__(256) void matrix_kernel() {
    __shared__ float4 sbi[ITILE];
    __shared__ float  sai[ITILE];
    int b  = blockIdx.y;
    int i0 = blockIdx.x * ITILE;
    int tid = threadIdx.x, lane = tid & 31, wid = tid >> 5;   // 8 warps

    // preload i-tile boxes into smem
    for (int q = tid; q < ITILE; q += 256) {
        int i = i0 + q;
        if (i < NMS_K) { sbi[q] = g_cbox[b * NMS_K + i]; sai[q] = g_carea[b * NMS_K + i]; }
        else           { sbi[q] = make_float4(0,0,0,0);  sai[q] = 0.f; }
    }
    __syncthreads();

    int ilim = min(ITILE, NMS_K - i0);
    int w0   = i0 >> 5;
    for (int w = w0 + wid; w < NWORDS; w += 8) {
        int j = w * 32 + lane;
        bool jv = j < NMS_K;
        float4 bj = jv ? g_cbox[b * NMS_K + j] : make_float4(0,0,0,0);
        float  aj = jv ? g_carea[b * NMS_K + j] : 0.f;
        size_t base = ((size_t)(b * NWORDS + w)) * PAD + i0;
        unsigned myw = 0;
        for (int ii = 0; ii < ilim; ii++) {
            int i = i0 + ii;
            float4 bi = sbi[ii];                      // broadcast (conflict-free)
            float  ai = sai[ii];
            float xx1 = fmaxf(bj.x, bi.x), yy1 = fmaxf(bj.y, bi.y);
            float xx2 = fminf(bj.z, bi.z), yy2 = fminf(bj.w, bi.w);
            float inter = fmaxf(xx2 - xx1, 0.f) * fmaxf(yy2 - yy1, 0.f);
            float uni   = aj - inter + ai;
            bool flag = jv && (j > i) && (__fdiv_rn(inter, uni) > NMS_TH);  // exact ref semantics
            unsigned bal = __ballot_sync(FULL, flag);
            if ((ii & 31) == lane) myw = bal;         // each lane keeps its slot's word
            if ((ii & 31) == 31) g_matT[base + (ii - 31) + lane] = myw;   // coalesced
        }
        if (ilim & 31) g_matT[base + (ilim & ~31) + lane] = myw;          // partial-tile flush
    }
}

// ---------------- greedy sweep: per-word latency batching ----------------
__global__ void sweep_kernel(float* __restrict__ out) {
    __shared__ unsigned validw[NWORDS];
    __shared__ int      s_acc[TOPK];
    __shared__ int      s_cnt;

    int b = blockIdx.x, tid = threadIdx.x, lane = tid & 31, wid = tid >> 5;

    // valid bitmask per word (score > 0)
    for (int w = wid; w < NWORDS; w += 8) {
        int i = w * 32 + lane;
        unsigned m = __ballot_sync(FULL, (i < NMS_K) && (g_cscore[b * NMS_K + i] > 0.0f));
        if (lane == 0) validw[w] = m;
    }
    __syncthreads();

    if (wid == 0) {
        int cnt = 0;
        for (int w = 0; w < NWORDS && cnt < TOPK; w++) {
            size_t base = ((size_t)(b * NWORDS + w)) * PAD;
            // suppression from previously accepted (parallel loads, one latency)
            unsigned rem = 0;
            for (int q = lane; q < cnt; q += 32)
                rem |= g_matT[base + s_acc[q]];
            rem = __reduce_or_sync(FULL, rem);
            // diagonal word: intra-word suppression rows (coalesced)
            unsigned pre = g_matT[base + w * 32 + lane];
            unsigned avail = validw[w] & ~rem;
            while (avail && cnt < TOPK) {
                int bit = __ffs(avail) - 1;
                int i = w * 32 + bit;
                if (lane == 0) s_acc[cnt] = i;
                cnt++;
                avail &= ~(1u << bit);
                avail &= ~__shfl_sync(FULL, pre, bit);
            }
            __syncwarp();
        }
        if (lane == 0) s_cnt = cnt;
    }
    __syncthreads();

    // parallel output emit (accepted order == emit order)
    int cnt = s_cnt;
    float* orow = out + ((size_t)b * 2 + 1) * TOPK * 5;   // class 1
    for (int t = tid; t < cnt; t += blockDim.x) {
        int i = s_acc[t];
        float4 bb = g_cbox[b * NMS_K + i];
        float  sc = g_cscore[b * NMS_K + i];
        float* r = orow + t * 5;
        r[0] = sc; r[1] = bb.x; r[2] = bb.y; r[3] = bb.z; r[4] = bb.w;
    }
}

// ---------------- launch ----------------
extern "C" void kernel_launch(void* const* d_in, const int* in_sizes, int n_in,
                              void* d_out, int out_size) {
    const float* loc   = (const float*)d_in[0];   // [B,P,4]
    const float* conf  = (const float*)d_in[1];   // [B,P,2]
    const float* prior = (const float*)d_in[2];   // [P,4]

    int P = in_sizes[2] / 4;
    int B = in_sizes[1] / (2 * P);
    if (B > B_MAX) B = B_MAX;
    if (P > P_MAX) P = P_MAX;

    float* out = (float*)d_out;

    static const size_t SORT_SMEM = (size_t)CAP * sizeof(unsigned long long);   // 64 KB
    cudaFuncSetAttribute(sort_kernel, cudaFuncAttributeMaxDynamicSharedMemorySize, (int)SORT_SMEM);

    init_kernel<<<256, 256>>>(out, out_size, B);

    dim3 gscore((P + 511) / 512, B);
    score_kernel<<<gscore, 256>>>(conf, P);

    cutoff_kernel<<<B, 256>>>();

    dim3 gcomp((P + 1023) / 1024, B);
    compact_kernel<<<gcomp, 256>>>(P);

    sort_kernel<<<B, 1024, SORT_SMEM>>>(loc, prior, P);

    dim3 gmat((NMS_K + ITILE - 1) / ITILE, B);
    matrix_kernel<<<gmat, 256>>>();

    sweep_kernel<<<B, 256>>>(out);
}